// round 11
// baseline (speedup 1.0000x reference)
#include <cuda_runtime.h>
#include <cuda_bf16.h>
#include <cstdint>

// Problem constants
#define BB   32
#define LL   512
#define DD   256
#define KKB  6
#define MTOK (BB * LL)   // 16384 tokens
#define HID  (4 * DD)    // 1024

// ---------------------------------------------------------------------------
// Scratch (static __device__ arrays: allocation-guard safe)
// ---------------------------------------------------------------------------
__device__ float g_emb[MTOK * DD];   // [L][B][D] layout (exact fp32)
__device__ float g_x  [MTOK * DD];   // [token][D], tf32-rounded
__device__ float g_h  [MTOK * HID];  // hidden activations (tf32-rounded)
__device__ float g_x2 [MTOK * DD];   // tf32-rounded
__device__ float g_x3 [MTOK * DD];   // tf32-rounded
__device__ float g_msg[MTOK * DD];   // exact fp32
// pre-rounded weights, concatenated: w1 | w2 | w3 | w4 | w5
#define WOFF_W1 0
#define WOFF_W2 262144
#define WOFF_W3 524288
#define WOFF_W4 786432
#define WOFF_W5 1048576
#define WTOTAL  1114112
__device__ float g_wr[WTOTAL];

// ---------------------------------------------------------------------------
// PTX helpers (sm_80-compatible only: cp.async, ldmatrix, mma.sync)
// ---------------------------------------------------------------------------
__device__ __forceinline__ uint32_t smem_u32(const void* p) {
    uint32_t a;
    asm("{ .reg .u64 t; cvta.to.shared.u64 t, %1; cvt.u32.u64 %0, t; }"
        : "=r"(a) : "l"(p));
    return a;
}

__device__ __forceinline__ void cpasync16(uint32_t s, const void* g) {
    asm volatile("cp.async.cg.shared.global [%0], [%1], 16;" :: "r"(s), "l"(g));
}
#define CP_COMMIT() asm volatile("cp.async.commit_group;" ::: "memory")
template<int N> __device__ __forceinline__ void cpwait() {
    asm volatile("cp.async.wait_group %0;" :: "n"(N) : "memory");
}

__device__ __forceinline__ void ldsm4(uint32_t* r, uint32_t addr) {
    asm volatile("ldmatrix.sync.aligned.m8n8.x4.shared.b16 {%0,%1,%2,%3}, [%4];"
        : "=r"(r[0]), "=r"(r[1]), "=r"(r[2]), "=r"(r[3]) : "r"(addr));
}

__device__ __forceinline__ float tf32r(float x) {
    uint32_t u = __float_as_uint(x);
    asm("cvt.rna.tf32.f32 %0, %0;" : "+r"(u));
    return __uint_as_float(u);
}

__device__ __forceinline__ void mma_tf32(float* d, const uint32_t* a, const uint32_t* b) {
    asm volatile(
        "mma.sync.aligned.m16n8k8.row.col.f32.tf32.tf32.f32 "
        "{%0,%1,%2,%3}, {%4,%5,%6,%7}, {%8,%9}, {%0,%1,%2,%3};"
        : "+f"(d[0]), "+f"(d[1]), "+f"(d[2]), "+f"(d[3])
        : "r"(a[0]), "r"(a[1]), "r"(a[2]), "r"(a[3]), "r"(b[0]), "r"(b[1]));
}

// ---------------------------------------------------------------------------
// Weight pre-rounding: round all 5 weight matrices to tf32 once.
// ---------------------------------------------------------------------------
__global__ __launch_bounds__(256) void round_w_kernel(
    const float* __restrict__ w1, const float* __restrict__ w2,
    const float* __restrict__ w3, const float* __restrict__ w4,
    const float* __restrict__ w5)
{
    const int i = blockIdx.x * 256 + threadIdx.x;      // float4 index
    const size_t idx = (size_t)i * 4;
    if (idx >= WTOTAL) return;
    const float* s; size_t base;
    if      (idx < WOFF_W2) { s = w1; base = WOFF_W1; }
    else if (idx < WOFF_W3) { s = w2; base = WOFF_W2; }
    else if (idx < WOFF_W4) { s = w3; base = WOFF_W3; }
    else if (idx < WOFF_W5) { s = w4; base = WOFF_W4; }
    else                    { s = w5; base = WOFF_W5; }
    float4 v = *(const float4*)(s + (idx - base));
    v.x = tf32r(v.x); v.y = tf32r(v.y); v.z = tf32r(v.z); v.w = tf32r(v.w);
    *(float4*)(g_wr + idx) = v;
}

// ---------------------------------------------------------------------------
// Embedding sum: g_emb exact; g_x tf32-rounded (GEMM input)
// ---------------------------------------------------------------------------
__global__ __launch_bounds__(256) void embed_kernel(
    const int* __restrict__ element, const int* __restrict__ aroma,
    const int* __restrict__ charge,  const int* __restrict__ segment,
    const int* __restrict__ rmask,
    const float* __restrict__ elem_emb, const float* __restrict__ charge_emb,
    const float* __restrict__ aroma_emb, const float* __restrict__ react_emb,
    const float* __restrict__ seg_emb,   const float* __restrict__ pe)
{
    const int token = blockIdx.x * 4 + (threadIdx.x >> 6);
    const int c     = (threadIdx.x & 63) * 4;
    const int b     = token >> 9;
    const int l     = token & (LL - 1);

    const int e  = __ldg(&element[token]);
    const int a  = __ldg(&aroma[token]);
    const int ch = __ldg(&charge[token]) + 6;
    const int s  = __ldg(&segment[token]);
    const int r  = __ldg(&rmask[token]);

    float4 v = *(const float4*)(elem_emb + e * DD + c);
    float4 t;
    t = *(const float4*)(pe + l * DD + c);          v.x += t.x; v.y += t.y; v.z += t.z; v.w += t.w;
    t = *(const float4*)(aroma_emb + a * DD + c);   v.x += t.x; v.y += t.y; v.z += t.z; v.w += t.w;
    t = *(const float4*)(charge_emb + ch * DD + c); v.x += t.x; v.y += t.y; v.z += t.z; v.w += t.w;
    t = *(const float4*)(seg_emb + s * DD + c);     v.x += t.x; v.y += t.y; v.z += t.z; v.w += t.w;
    t = *(const float4*)(react_emb + r * DD + c);   v.x += t.x; v.y += t.y; v.z += t.z; v.w += t.w;

    *(float4*)(g_emb + (l * BB + b) * DD + c) = v;
    float4 q = make_float4(tf32r(v.x), tf32r(v.y), tf32r(v.z), tf32r(v.w));
    *(float4*)(g_x + token * DD + c) = q;
}

// ---------------------------------------------------------------------------
// TF32 tensor-core GEMM via mma.sync:  C = A @ W^T + bias (+res) (+relu)
// Inputs pre-rounded to tf32 -> no cvt in mainloop.
// BM=128, BN=128, BK=32, 3-stage cp.async pipeline, 512 threads (16 warps),
// warp tile 32x32 (4x4 warp grid). Small per-thread state (acc=32 regs)
// leaves ~40 free regs for compiler software-pipelining of ldsm under mma.
// WOUT: round the stored output to tf32 (when it feeds another GEMM).
// ---------------------------------------------------------------------------
#define BM     128
#define BN     128
#define BK     32
#define STAGES 3
#define STG_SZ 32768                  // (BM + BN) * BK * 4
#define SMEM_SZ (STAGES * STG_SZ)     // 98304
#define NTHR   512

template<int K, bool RELU, bool RES, bool WOUT>
__global__ __launch_bounds__(NTHR, 1) void tgemm_kernel(
    const float* __restrict__ A, const float* __restrict__ W,
    const float* __restrict__ bias, const float* __restrict__ res,
    float* __restrict__ C, int N)
{
    extern __shared__ char smem[];
    const uint32_t sbase = smem_u32(smem);
    const int tid = threadIdx.x;
    const int wid = tid >> 5;
    const int lid = tid & 31;
    const int wm  = wid & 3;        // warp row: 4 x 32
    const int wn  = wid >> 2;       // warp col: 4 x 32

    const int rowBase = blockIdx.y * BM;
    const int colBase = blockIdx.x * BN;

    constexpr int NC = K / BK;

    // stage loader: A tile 128x32 f32 (16KB) + B tile 128x32 f32 (16KB)
    // smem row = 128B (32 floats), xor swizzle on 16B chunks within the row:
    // phys_chunk = ck ^ (row & 7) -> ldmatrix conflict-free
    auto load_stage = [&](int c, int buf) {
        const int k0 = c * BK;
        const uint32_t sA = sbase + buf * STG_SZ;
        const uint32_t sB = sA + 16384;
        const float* Ag = A + (size_t)rowBase * K + k0;
        const float* Wg = W + (size_t)colBase * K + k0;
        #pragma unroll
        for (int p = 0; p < 2; p++) {              // 1024 chunks / 512 thr
            int v = tid + p * NTHR;
            int r = v >> 3, ck = v & 7;
            cpasync16(sA + r * 128 + ((ck ^ (r & 7)) * 16),
                      Ag + (size_t)r * K + ck * 4);
        }
        #pragma unroll
        for (int p = 0; p < 2; p++) {
            int v = tid + p * NTHR;
            int r = v >> 3, ck = v & 7;
            cpasync16(sB + r * 128 + ((ck ^ (r & 7)) * 16),
                      Wg + (size_t)r * K + ck * 4);
        }
        CP_COMMIT();
    };

    float acc[2][4][4];
    #pragma unroll
    for (int mi = 0; mi < 2; mi++)
        #pragma unroll
        for (int ni = 0; ni < 4; ni++)
            #pragma unroll
            for (int j = 0; j < 4; j++) acc[mi][ni][j] = 0.f;

    // per-thread ldmatrix address components (row stride 128B, 8 chunks/row)
    const int t   = lid & 7;
    const int sel = lid >> 3;
    int aRow[2], aXor[2];
    #pragma unroll
    for (int mi = 0; mi < 2; mi++) {
        int r = wm * 32 + mi * 16 + (sel & 1) * 8 + t;
        aRow[mi] = r * 128;
        aXor[mi] = r & 7;
    }
    const int aCk = sel >> 1;
    int bRow[2], bXor[2];
    #pragma unroll
    for (int np = 0; np < 2; np++) {
        int r = wn * 32 + np * 16 + (sel >> 1) * 8 + t;
        bRow[np] = r * 128;
        bXor[np] = r & 7;
    }
    const int bCk = sel & 1;

    // prologue: stages 0, 1
    load_stage(0, 0);
    if (NC > 1) load_stage(1, 1);
    else        CP_COMMIT();

    int cbuf = 0;   // stage holding chunk c
    for (int c = 0; c < NC; c++) {      // ROLLED: compile-time safe
        cpwait<STAGES - 2>();
        __syncthreads();
        if (c + STAGES - 1 < NC) {
            int nbuf = cbuf + (STAGES - 1);
            if (nbuf >= STAGES) nbuf -= STAGES;
            load_stage(c + STAGES - 1, nbuf);
        } else {
            CP_COMMIT();
        }

        const uint32_t sA = sbase + cbuf * STG_SZ;
        const uint32_t sB = sA + 16384;

        #pragma unroll
        for (int ks = 0; ks < 4; ks++) {           // 4 x K=8 per chunk
            uint32_t af[2][4], bf[2][4];
            #pragma unroll
            for (int mi = 0; mi < 2; mi++) {
                int ck = ks * 2 + aCk;
                ldsm4(af[mi], sA + aRow[mi] + ((ck ^ aXor[mi]) * 16));
            }
            #pragma unroll
            for (int np = 0; np < 2; np++) {
                int ck = ks * 2 + bCk;
                ldsm4(bf[np], sB + bRow[np] + ((ck ^ bXor[np]) * 16));
            }
            #pragma unroll
            for (int mi = 0; mi < 2; mi++)
                #pragma unroll
                for (int ni = 0; ni < 4; ni++)
                    mma_tf32(acc[mi][ni], af[mi], &bf[ni >> 1][(ni & 1) * 2]);
        }

        if (++cbuf == STAGES) cbuf = 0;
    }

    // ---- epilogue ----
    const int g  = lid >> 2;
    const int tg = lid & 3;
    #pragma unroll
    for (int mi = 0; mi < 2; mi++) {
        const int row0 = rowBase + wm * 32 + mi * 16 + g;
        const int row1 = row0 + 8;
        #pragma unroll
        for (int ni = 0; ni < 4; ni++) {
            const int col = colBase + wn * 32 + ni * 8 + tg * 2;
            float bx = __ldg(&bias[col]), by = __ldg(&bias[col + 1]);
            float2 v0 = make_float2(acc[mi][ni][0] + bx, acc[mi][ni][1] + by);
            float2 v1 = make_float2(acc[mi][ni][2] + bx, acc[mi][ni][3] + by);
            if (RES) {
                float2 r0 = *(const float2*)(res + (size_t)row0 * N + col);
                float2 r1 = *(const float2*)(res + (size_t)row1 * N + col);
                v0.x += r0.x; v0.y += r0.y; v1.x += r1.x; v1.y += r1.y;
            }
            if (RELU) {
                v0.x = fmaxf(v0.x, 0.f); v0.y = fmaxf(v0.y, 0.f);
                v1.x = fmaxf(v1.x, 0.f); v1.y = fmaxf(v1.y, 0.f);
            }
            if (WOUT) {
                v0.x = tf32r(v0.x); v0.y = tf32r(v0.y);
                v1.x = tf32r(v1.x); v1.y = tf32r(v1.y);
            }
            *(float2*)(C + (size_t)row0 * N + col) = v0;
            *(float2*)(C + (size_t)row1 * N + col) = v1;
        }
    }
}

// ---------------------------------------------------------------------------
// Bond aggregation + output
// ---------------------------------------------------------------------------
__global__ __launch_bounds__(256) void agg_kernel(
    const int* __restrict__ bond, float* __restrict__ out)
{
    const int token = blockIdx.x * 4 + (threadIdx.x >> 6);
    const int c     = (threadIdx.x & 63) * 4;
    const int b     = token >> 9;
    const int l     = token & (LL - 1);

    float4 acc = *(const float4*)(g_emb + (l * BB + b) * DD + c);
    const int* bd = bond + token * KKB;
    #pragma unroll
    for (int k = 0; k < KKB; k++) {
        const int j = __ldg(&bd[k]);
        if (j != l) {
            float4 m = *(const float4*)(g_msg + ((size_t)b * LL + j) * DD + c);
            acc.x += m.x; acc.y += m.y; acc.z += m.z; acc.w += m.w;
        }
    }
    *(float4*)(out + (l * BB + b) * DD + c) = acc;
}

// ---------------------------------------------------------------------------
// Launch (graph-capturable)
// ---------------------------------------------------------------------------
extern "C" void kernel_launch(void* const* d_in, const int* in_sizes, int n_in,
                              void* d_out, int out_size)
{
    const int*   element    = (const int*)  d_in[0];
    const int*   bond       = (const int*)  d_in[1];
    const int*   aroma      = (const int*)  d_in[2];
    const int*   charge     = (const int*)  d_in[3];
    const int*   segment    = (const int*)  d_in[4];
    const int*   rmask      = (const int*)  d_in[5];
    const float* elem_emb   = (const float*)d_in[6];
    const float* charge_emb = (const float*)d_in[7];
    const float* aroma_emb  = (const float*)d_in[8];
    const float* react_emb  = (const float*)d_in[9];
    const float* seg_emb    = (const float*)d_in[10];
    const float* pe         = (const float*)d_in[11];
    const float* w1 = (const float*)d_in[12];
    const float* b1 = (const float*)d_in[13];
    const float* w2 = (const float*)d_in[14];
    const float* b2 = (const float*)d_in[15];
    const float* w3 = (const float*)d_in[16];
    const float* b3 = (const float*)d_in[17];
    const float* w4 = (const float*)d_in[18];
    const float* b4 = (const float*)d_in[19];
    const float* w5 = (const float*)d_in[20];
    const float* b5 = (const float*)d_in[21];

    float *x, *h, *x2, *x3, *msg, *wr;
    cudaGetSymbolAddress((void**)&x,   g_x);
    cudaGetSymbolAddress((void**)&h,   g_h);
    cudaGetSymbolAddress((void**)&x2,  g_x2);
    cudaGetSymbolAddress((void**)&x3,  g_x3);
    cudaGetSymbolAddress((void**)&msg, g_msg);
    cudaGetSymbolAddress((void**)&wr,  g_wr);

    cudaFuncSetAttribute(tgemm_kernel<DD,  true,  false, true >,
                         cudaFuncAttributeMaxDynamicSharedMemorySize, SMEM_SZ);
    cudaFuncSetAttribute(tgemm_kernel<HID, false, true,  true >,
                         cudaFuncAttributeMaxDynamicSharedMemorySize, SMEM_SZ);
    cudaFuncSetAttribute(tgemm_kernel<DD,  false, false, false>,
                         cudaFuncAttributeMaxDynamicSharedMemorySize, SMEM_SZ);

    // 0) pre-round weights to tf32
    round_w_kernel<<<(WTOTAL / 4 + 255) / 256, 256>>>(w1, w2, w3, w4, w5);

    // 1) embedding sum
    embed_kernel<<<MTOK / 4, 256>>>(element, aroma, charge, segment, rmask,
                                    elem_emb, charge_emb, aroma_emb,
                                    react_emb, seg_emb, pe);

    // 2) MLP block 1: h = relu(x @ w1^T + b1); x2 = x + h @ w2^T + b2
    tgemm_kernel<DD,  true,  false, true ><<<dim3(HID / BN, MTOK / BM), NTHR, SMEM_SZ>>>(
        x, wr + WOFF_W1, b1, nullptr, h, HID);
    tgemm_kernel<HID, false, true,  true ><<<dim3(DD / BN,  MTOK / BM), NTHR, SMEM_SZ>>>(
        h, wr + WOFF_W2, b2, x, x2, DD);

    // 3) MLP block 2
    tgemm_kernel<DD,  true,  false, true ><<<dim3(HID / BN, MTOK / BM), NTHR, SMEM_SZ>>>(
        x2, wr + WOFF_W3, b3, nullptr, h, HID);
    tgemm_kernel<HID, false, true,  true ><<<dim3(DD / BN,  MTOK / BM), NTHR, SMEM_SZ>>>(
        h, wr + WOFF_W4, b4, x2, x3, DD);

    // 4) msg = x3 @ w5^T + b5  (exact fp32 store)
    tgemm_kernel<DD,  false, false, false><<<dim3(DD / BN,  MTOK / BM), NTHR, SMEM_SZ>>>(
        x3, wr + WOFF_W5, b5, nullptr, msg, DD);

    // 5) out = emb + masked bond aggregation
    agg_kernel<<<MTOK / 4, 256>>>(bond, (float*)d_out);
}

// round 12
// speedup vs baseline: 1.0509x; 1.0509x over previous
#include <cuda_runtime.h>
#include <cuda_bf16.h>
#include <cstdint>

// Problem constants
#define BB   32
#define LL   512
#define DD   256
#define KKB  6
#define MTOK (BB * LL)   // 16384 tokens
#define HID  (4 * DD)    // 1024

// ---------------------------------------------------------------------------
// Scratch (static __device__ arrays: allocation-guard safe)
// ---------------------------------------------------------------------------
__device__ float g_emb[MTOK * DD];   // [L][B][D] layout (exact fp32)
__device__ float g_x  [MTOK * DD];   // [token][D], tf32-rounded
__device__ float g_h  [MTOK * HID];  // hidden activations (tf32-rounded)
__device__ float g_x2 [MTOK * DD];   // tf32-rounded
__device__ float g_x3 [MTOK * DD];   // tf32-rounded
__device__ float g_msg[MTOK * DD];   // exact fp32
// pre-rounded weights, concatenated: w1 | w2 | w3 | w4 | w5
#define WOFF_W1 0
#define WOFF_W2 262144
#define WOFF_W3 524288
#define WOFF_W4 786432
#define WOFF_W5 1048576
#define WTOTAL  1114112
__device__ float g_wr[WTOTAL];

// ---------------------------------------------------------------------------
// PTX helpers (sm_80-compatible only: cp.async, ldmatrix, mma.sync)
// ---------------------------------------------------------------------------
__device__ __forceinline__ uint32_t smem_u32(const void* p) {
    uint32_t a;
    asm("{ .reg .u64 t; cvta.to.shared.u64 t, %1; cvt.u32.u64 %0, t; }"
        : "=r"(a) : "l"(p));
    return a;
}

__device__ __forceinline__ void cpasync16(uint32_t s, const void* g) {
    asm volatile("cp.async.cg.shared.global [%0], [%1], 16;" :: "r"(s), "l"(g));
}
#define CP_COMMIT() asm volatile("cp.async.commit_group;" ::: "memory")
template<int N> __device__ __forceinline__ void cpwait() {
    asm volatile("cp.async.wait_group %0;" :: "n"(N) : "memory");
}

__device__ __forceinline__ void ldsm4(uint32_t* r, uint32_t addr) {
    asm volatile("ldmatrix.sync.aligned.m8n8.x4.shared.b16 {%0,%1,%2,%3}, [%4];"
        : "=r"(r[0]), "=r"(r[1]), "=r"(r[2]), "=r"(r[3]) : "r"(addr));
}

__device__ __forceinline__ float tf32r(float x) {
    uint32_t u = __float_as_uint(x);
    asm("cvt.rna.tf32.f32 %0, %0;" : "+r"(u));
    return __uint_as_float(u);
}

__device__ __forceinline__ void mma_tf32(float* d, const uint32_t* a, const uint32_t* b) {
    asm volatile(
        "mma.sync.aligned.m16n8k8.row.col.f32.tf32.tf32.f32 "
        "{%0,%1,%2,%3}, {%4,%5,%6,%7}, {%8,%9}, {%0,%1,%2,%3};"
        : "+f"(d[0]), "+f"(d[1]), "+f"(d[2]), "+f"(d[3])
        : "r"(a[0]), "r"(a[1]), "r"(a[2]), "r"(a[3]), "r"(b[0]), "r"(b[1]));
}

// ---------------------------------------------------------------------------
// Weight pre-rounding: round all 5 weight matrices to tf32 once.
// ---------------------------------------------------------------------------
__global__ __launch_bounds__(256) void round_w_kernel(
    const float* __restrict__ w1, const float* __restrict__ w2,
    const float* __restrict__ w3, const float* __restrict__ w4,
    const float* __restrict__ w5)
{
    const int i = blockIdx.x * 256 + threadIdx.x;      // float4 index
    const size_t idx = (size_t)i * 4;
    if (idx >= WTOTAL) return;
    const float* s; size_t base;
    if      (idx < WOFF_W2) { s = w1; base = WOFF_W1; }
    else if (idx < WOFF_W3) { s = w2; base = WOFF_W2; }
    else if (idx < WOFF_W4) { s = w3; base = WOFF_W3; }
    else if (idx < WOFF_W5) { s = w4; base = WOFF_W4; }
    else                    { s = w5; base = WOFF_W5; }
    float4 v = *(const float4*)(s + (idx - base));
    v.x = tf32r(v.x); v.y = tf32r(v.y); v.z = tf32r(v.z); v.w = tf32r(v.w);
    *(float4*)(g_wr + idx) = v;
}

// ---------------------------------------------------------------------------
// Embedding sum: g_emb exact; g_x tf32-rounded (GEMM input)
// ---------------------------------------------------------------------------
__global__ __launch_bounds__(256) void embed_kernel(
    const int* __restrict__ element, const int* __restrict__ aroma,
    const int* __restrict__ charge,  const int* __restrict__ segment,
    const int* __restrict__ rmask,
    const float* __restrict__ elem_emb, const float* __restrict__ charge_emb,
    const float* __restrict__ aroma_emb, const float* __restrict__ react_emb,
    const float* __restrict__ seg_emb,   const float* __restrict__ pe)
{
    const int token = blockIdx.x * 4 + (threadIdx.x >> 6);
    const int c     = (threadIdx.x & 63) * 4;
    const int b     = token >> 9;
    const int l     = token & (LL - 1);

    const int e  = __ldg(&element[token]);
    const int a  = __ldg(&aroma[token]);
    const int ch = __ldg(&charge[token]) + 6;
    const int s  = __ldg(&segment[token]);
    const int r  = __ldg(&rmask[token]);

    float4 v = *(const float4*)(elem_emb + e * DD + c);
    float4 t;
    t = *(const float4*)(pe + l * DD + c);          v.x += t.x; v.y += t.y; v.z += t.z; v.w += t.w;
    t = *(const float4*)(aroma_emb + a * DD + c);   v.x += t.x; v.y += t.y; v.z += t.z; v.w += t.w;
    t = *(const float4*)(charge_emb + ch * DD + c); v.x += t.x; v.y += t.y; v.z += t.z; v.w += t.w;
    t = *(const float4*)(seg_emb + s * DD + c);     v.x += t.x; v.y += t.y; v.z += t.z; v.w += t.w;
    t = *(const float4*)(react_emb + r * DD + c);   v.x += t.x; v.y += t.y; v.z += t.z; v.w += t.w;

    *(float4*)(g_emb + (l * BB + b) * DD + c) = v;
    float4 q = make_float4(tf32r(v.x), tf32r(v.y), tf32r(v.z), tf32r(v.w));
    *(float4*)(g_x + token * DD + c) = q;
}

// ---------------------------------------------------------------------------
// TF32 tensor-core GEMM via mma.sync:  C = A @ W^T + bias (+res) (+relu)
// Inputs pre-rounded to tf32 -> no cvt in mainloop.
// CTA tile 128x256, 8 warps (2x4 grid), WARP TILE 64x64 (min fragment
// bytes/MAC = 0.125), BK=32, 4-stage cp.async pipeline (192KB smem,
// 1 CTA/SM), ~220 regs, manual fragment double-buffering: ldsm of ks+1
// issues under the 32-mma burst of ks.
// WOUT: round the stored output to tf32 (when it feeds another GEMM).
// ---------------------------------------------------------------------------
#define BM     128
#define BN     256
#define BK     32
#define STAGES 4
#define STG_SZ 49152                  // (BM + BN) * BK * 4
#define SMEM_SZ (STAGES * STG_SZ)     // 196608
#define NTHR   256

template<int K, bool RELU, bool RES, bool WOUT>
__global__ __launch_bounds__(NTHR, 1) void tgemm_kernel(
    const float* __restrict__ A, const float* __restrict__ W,
    const float* __restrict__ bias, const float* __restrict__ res,
    float* __restrict__ C, int N)
{
    extern __shared__ char smem[];
    const uint32_t sbase = smem_u32(smem);
    const int tid = threadIdx.x;
    const int wid = tid >> 5;
    const int lid = tid & 31;
    const int wm  = wid & 1;        // warp row: 2 x 64
    const int wn  = wid >> 1;       // warp col: 4 x 64

    const int rowBase = blockIdx.y * BM;
    const int colBase = blockIdx.x * BN;

    constexpr int NC = K / BK;

    // stage loader: A tile 128x32 f32 (16KB) + B tile 256x32 f32 (32KB)
    // smem row = 128B (32 floats), xor swizzle on 16B chunks:
    // phys_chunk = ck ^ (row & 7) -> ldmatrix conflict-free
    auto load_stage = [&](int c, int buf) {
        const int k0 = c * BK;
        const uint32_t sA = sbase + buf * STG_SZ;
        const uint32_t sB = sA + 16384;
        const float* Ag = A + (size_t)rowBase * K + k0;
        const float* Wg = W + (size_t)colBase * K + k0;
        #pragma unroll
        for (int p = 0; p < 4; p++) {              // A: 1024 chunks / 256 thr
            int v = tid + p * NTHR;
            int r = v >> 3, ck = v & 7;
            cpasync16(sA + r * 128 + ((ck ^ (r & 7)) * 16),
                      Ag + (size_t)r * K + ck * 4);
        }
        #pragma unroll
        for (int p = 0; p < 8; p++) {              // B: 2048 chunks / 256 thr
            int v = tid + p * NTHR;
            int r = v >> 3, ck = v & 7;
            cpasync16(sB + r * 128 + ((ck ^ (r & 7)) * 16),
                      Wg + (size_t)r * K + ck * 4);
        }
        CP_COMMIT();
    };

    float acc[4][8][4];   // 128 regs: warp tile 64 (4x16) x 64 (8x8)
    #pragma unroll
    for (int mi = 0; mi < 4; mi++)
        #pragma unroll
        for (int ni = 0; ni < 8; ni++)
            #pragma unroll
            for (int j = 0; j < 4; j++) acc[mi][ni][j] = 0.f;

    // per-thread ldmatrix address components (row stride 128B, 8 chunks/row)
    const int t   = lid & 7;
    const int sel = lid >> 3;
    int aRow[4], aXor[4];
    #pragma unroll
    for (int mi = 0; mi < 4; mi++) {
        int r = wm * 64 + mi * 16 + (sel & 1) * 8 + t;
        aRow[mi] = r * 128;
        aXor[mi] = r & 7;
    }
    const int aCk = sel >> 1;
    int bRow[4], bXor[4];
    #pragma unroll
    for (int np = 0; np < 4; np++) {
        int r = wn * 64 + np * 16 + (sel >> 1) * 8 + t;
        bRow[np] = r * 128;
        bXor[np] = r & 7;
    }
    const int bCk = sel & 1;

    // prologue: stages 0..2
    load_stage(0, 0);
    load_stage(1, 1);
    load_stage(2, 2);

    int cbuf = 0;   // stage holding chunk c
    for (int c = 0; c < NC; c++) {      // rolled (compile-time safe)
        cpwait<STAGES - 2>();
        __syncthreads();
        if (c + STAGES - 1 < NC) {
            int nbuf = cbuf + (STAGES - 1);
            if (nbuf >= STAGES) nbuf -= STAGES;
            load_stage(c + STAGES - 1, nbuf);
        } else {
            CP_COMMIT();
        }

        const uint32_t sA = sbase + cbuf * STG_SZ;
        const uint32_t sB = sA + 16384;

        uint32_t af[2][4][4], bf[2][4][4];   // fragment double buffers

        // load ks=0 fragments into buffer 0
        #pragma unroll
        for (int mi = 0; mi < 4; mi++)
            ldsm4(af[0][mi], sA + aRow[mi] + ((aCk ^ aXor[mi]) * 16));
        #pragma unroll
        for (int np = 0; np < 4; np++)
            ldsm4(bf[0][np], sB + bRow[np] + ((bCk ^ bXor[np]) * 16));

        #pragma unroll
        for (int ks = 0; ks < 4; ks++) {
            const int cur = ks & 1, nxt = cur ^ 1;
            if (ks < 3) {   // prefetch ks+1 fragments under this mma burst
                const int ck = (ks + 1) * 2;
                #pragma unroll
                for (int mi = 0; mi < 4; mi++)
                    ldsm4(af[nxt][mi], sA + aRow[mi] + (((ck + aCk) ^ aXor[mi]) * 16));
                #pragma unroll
                for (int np = 0; np < 4; np++)
                    ldsm4(bf[nxt][np], sB + bRow[np] + (((ck + bCk) ^ bXor[np]) * 16));
            }
            #pragma unroll
            for (int mi = 0; mi < 4; mi++)
                #pragma unroll
                for (int ni = 0; ni < 8; ni++)
                    mma_tf32(acc[mi][ni], af[cur][mi], &bf[cur][ni >> 1][(ni & 1) * 2]);
        }

        if (++cbuf == STAGES) cbuf = 0;
    }

    // ---- epilogue ----
    const int g  = lid >> 2;
    const int tg = lid & 3;
    #pragma unroll
    for (int mi = 0; mi < 4; mi++) {
        const int row0 = rowBase + wm * 64 + mi * 16 + g;
        const int row1 = row0 + 8;
        #pragma unroll
        for (int ni = 0; ni < 8; ni++) {
            const int col = colBase + wn * 64 + ni * 8 + tg * 2;
            float bx = __ldg(&bias[col]), by = __ldg(&bias[col + 1]);
            float2 v0 = make_float2(acc[mi][ni][0] + bx, acc[mi][ni][1] + by);
            float2 v1 = make_float2(acc[mi][ni][2] + bx, acc[mi][ni][3] + by);
            if (RES) {
                float2 r0 = *(const float2*)(res + (size_t)row0 * N + col);
                float2 r1 = *(const float2*)(res + (size_t)row1 * N + col);
                v0.x += r0.x; v0.y += r0.y; v1.x += r1.x; v1.y += r1.y;
            }
            if (RELU) {
                v0.x = fmaxf(v0.x, 0.f); v0.y = fmaxf(v0.y, 0.f);
                v1.x = fmaxf(v1.x, 0.f); v1.y = fmaxf(v1.y, 0.f);
            }
            if (WOUT) {
                v0.x = tf32r(v0.x); v0.y = tf32r(v0.y);
                v1.x = tf32r(v1.x); v1.y = tf32r(v1.y);
            }
            *(float2*)(C + (size_t)row0 * N + col) = v0;
            *(float2*)(C + (size_t)row1 * N + col) = v1;
        }
    }
}

// ---------------------------------------------------------------------------
// Bond aggregation + output
// ---------------------------------------------------------------------------
__global__ __launch_bounds__(256) void agg_kernel(
    const int* __restrict__ bond, float* __restrict__ out)
{
    const int token = blockIdx.x * 4 + (threadIdx.x >> 6);
    const int c     = (threadIdx.x & 63) * 4;
    const int b     = token >> 9;
    const int l     = token & (LL - 1);

    float4 acc = *(const float4*)(g_emb + (l * BB + b) * DD + c);
    const int* bd = bond + token * KKB;
    #pragma unroll
    for (int k = 0; k < KKB; k++) {
        const int j = __ldg(&bd[k]);
        if (j != l) {
            float4 m = *(const float4*)(g_msg + ((size_t)b * LL + j) * DD + c);
            acc.x += m.x; acc.y += m.y; acc.z += m.z; acc.w += m.w;
        }
    }
    *(float4*)(out + (l * BB + b) * DD + c) = acc;
}

// ---------------------------------------------------------------------------
// Launch (graph-capturable)
// ---------------------------------------------------------------------------
extern "C" void kernel_launch(void* const* d_in, const int* in_sizes, int n_in,
                              void* d_out, int out_size)
{
    const int*   element    = (const int*)  d_in[0];
    const int*   bond       = (const int*)  d_in[1];
    const int*   aroma      = (const int*)  d_in[2];
    const int*   charge     = (const int*)  d_in[3];
    const int*   segment    = (const int*)  d_in[4];
    const int*   rmask      = (const int*)  d_in[5];
    const float* elem_emb   = (const float*)d_in[6];
    const float* charge_emb = (const float*)d_in[7];
    const float* aroma_emb  = (const float*)d_in[8];
    const float* react_emb  = (const float*)d_in[9];
    const float* seg_emb    = (const float*)d_in[10];
    const float* pe         = (const float*)d_in[11];
    const float* w1 = (const float*)d_in[12];
    const float* b1 = (const float*)d_in[13];
    const float* w2 = (const float*)d_in[14];
    const float* b2 = (const float*)d_in[15];
    const float* w3 = (const float*)d_in[16];
    const float* b3 = (const float*)d_in[17];
    const float* w4 = (const float*)d_in[18];
    const float* b4 = (const float*)d_in[19];
    const float* w5 = (const float*)d_in[20];
    const float* b5 = (const float*)d_in[21];

    float *x, *h, *x2, *x3, *msg, *wr;
    cudaGetSymbolAddress((void**)&x,   g_x);
    cudaGetSymbolAddress((void**)&h,   g_h);
    cudaGetSymbolAddress((void**)&x2,  g_x2);
    cudaGetSymbolAddress((void**)&x3,  g_x3);
    cudaGetSymbolAddress((void**)&msg, g_msg);
    cudaGetSymbolAddress((void**)&wr,  g_wr);

    cudaFuncSetAttribute(tgemm_kernel<DD,  true,  false, true >,
                         cudaFuncAttributeMaxDynamicSharedMemorySize, SMEM_SZ);
    cudaFuncSetAttribute(tgemm_kernel<HID, false, true,  true >,
                         cudaFuncAttributeMaxDynamicSharedMemorySize, SMEM_SZ);
    cudaFuncSetAttribute(tgemm_kernel<DD,  false, false, false>,
                         cudaFuncAttributeMaxDynamicSharedMemorySize, SMEM_SZ);

    // 0) pre-round weights to tf32
    round_w_kernel<<<(WTOTAL / 4 + 255) / 256, 256>>>(w1, w2, w3, w4, w5);

    // 1) embedding sum
    embed_kernel<<<MTOK / 4, 256>>>(element, aroma, charge, segment, rmask,
                                    elem_emb, charge_emb, aroma_emb,
                                    react_emb, seg_emb, pe);

    // 2) MLP block 1: h = relu(x @ w1^T + b1); x2 = x + h @ w2^T + b2
    tgemm_kernel<DD,  true,  false, true ><<<dim3(HID / BN, MTOK / BM), NTHR, SMEM_SZ>>>(
        x, wr + WOFF_W1, b1, nullptr, h, HID);
    tgemm_kernel<HID, false, true,  true ><<<dim3(DD / BN,  MTOK / BM), NTHR, SMEM_SZ>>>(
        h, wr + WOFF_W2, b2, x, x2, DD);

    // 3) MLP block 2
    tgemm_kernel<DD,  true,  false, true ><<<dim3(HID / BN, MTOK / BM), NTHR, SMEM_SZ>>>(
        x2, wr + WOFF_W3, b3, nullptr, h, HID);
    tgemm_kernel<HID, false, true,  true ><<<dim3(DD / BN,  MTOK / BM), NTHR, SMEM_SZ>>>(
        h, wr + WOFF_W4, b4, x2, x3, DD);

    // 4) msg = x3 @ w5^T + b5  (exact fp32 store)
    tgemm_kernel<DD,  false, false, false><<<dim3(DD / BN,  MTOK / BM), NTHR, SMEM_SZ>>>(
        x3, wr + WOFF_W5, b5, nullptr, msg, DD);

    // 5) out = emb + masked bond aggregation
    agg_kernel<<<MTOK / 4, 256>>>(bond, (float*)d_out);
}

// round 14
// speedup vs baseline: 1.9081x; 1.8156x over previous
#include <cuda_runtime.h>
#include <cuda_fp16.h>
#include <cstdint>

// Problem constants
#define BB   32
#define LL   512
#define DD   256
#define KKB  6
#define MTOK (BB * LL)   // 16384 tokens
#define HID  (4 * DD)    // 1024

// ---------------------------------------------------------------------------
// Scratch (static __device__ arrays: allocation-guard safe)
// ---------------------------------------------------------------------------
__device__ float  g_emb[MTOK * DD];   // [L][B][D] layout (exact fp32)
__device__ __half g_xh [MTOK * DD];   // [token][D], fp16 (GEMM input)
__device__ __half g_h  [MTOK * HID];  // hidden activations fp16
__device__ __half g_x2 [MTOK * DD];   // fp16
__device__ __half g_x3 [MTOK * DD];   // fp16
__device__ float  g_msg[MTOK * DD];   // exact fp32
// fp16 weights, concatenated: w1 | w2 | w3 | w4 | w5
#define WOFF_W1 0
#define WOFF_W2 262144
#define WOFF_W3 524288
#define WOFF_W4 786432
#define WOFF_W5 1048576
#define WTOTAL  1114112
__device__ __half g_wh[WTOTAL];

// ---------------------------------------------------------------------------
// PTX helpers (sm_80-compatible only: cp.async, ldmatrix, mma.sync)
// ---------------------------------------------------------------------------
__device__ __forceinline__ uint32_t smem_u32(const void* p) {
    uint32_t a;
    asm("{ .reg .u64 t; cvta.to.shared.u64 t, %1; cvt.u32.u64 %0, t; }"
        : "=r"(a) : "l"(p));
    return a;
}

__device__ __forceinline__ void cpasync16(uint32_t s, const void* g) {
    asm volatile("cp.async.cg.shared.global [%0], [%1], 16;" :: "r"(s), "l"(g));
}
#define CP_COMMIT() asm volatile("cp.async.commit_group;" ::: "memory")
template<int N> __device__ __forceinline__ void cpwait() {
    asm volatile("cp.async.wait_group %0;" :: "n"(N) : "memory");
}

__device__ __forceinline__ void ldsm4(uint32_t* r, uint32_t addr) {
    asm volatile("ldmatrix.sync.aligned.m8n8.x4.shared.b16 {%0,%1,%2,%3}, [%4];"
        : "=r"(r[0]), "=r"(r[1]), "=r"(r[2]), "=r"(r[3]) : "r"(addr));
}

// m16n8k16 fp16 mma, fp32 accumulate
__device__ __forceinline__ void mma_f16(float* d, const uint32_t* a, const uint32_t* b) {
    asm volatile(
        "mma.sync.aligned.m16n8k16.row.col.f32.f16.f16.f32 "
        "{%0,%1,%2,%3}, {%4,%5,%6,%7}, {%8,%9}, {%0,%1,%2,%3};"
        : "+f"(d[0]), "+f"(d[1]), "+f"(d[2]), "+f"(d[3])
        : "r"(a[0]), "r"(a[1]), "r"(a[2]), "r"(a[3]), "r"(b[0]), "r"(b[1]));
}

// ---------------------------------------------------------------------------
// Weight conversion: fp32 -> fp16 once.
// ---------------------------------------------------------------------------
__global__ __launch_bounds__(256) void conv_w_kernel(
    const float* __restrict__ w1, const float* __restrict__ w2,
    const float* __restrict__ w3, const float* __restrict__ w4,
    const float* __restrict__ w5)
{
    const int i = blockIdx.x * 256 + threadIdx.x;      // float4 index
    const size_t idx = (size_t)i * 4;
    if (idx >= WTOTAL) return;
    const float* s; size_t base;
    if      (idx < WOFF_W2) { s = w1; base = WOFF_W1; }
    else if (idx < WOFF_W3) { s = w2; base = WOFF_W2; }
    else if (idx < WOFF_W4) { s = w3; base = WOFF_W3; }
    else if (idx < WOFF_W5) { s = w4; base = WOFF_W4; }
    else                    { s = w5; base = WOFF_W5; }
    float4 v = *(const float4*)(s + (idx - base));
    __half2 h0 = __float22half2_rn(make_float2(v.x, v.y));
    __half2 h1 = __float22half2_rn(make_float2(v.z, v.w));
    *(__half2*)(g_wh + idx)     = h0;
    *(__half2*)(g_wh + idx + 2) = h1;
}

// ---------------------------------------------------------------------------
// Embedding sum: g_emb exact fp32; g_xh fp16 (GEMM input)
// ---------------------------------------------------------------------------
__global__ __launch_bounds__(256) void embed_kernel(
    const int* __restrict__ element, const int* __restrict__ aroma,
    const int* __restrict__ charge,  const int* __restrict__ segment,
    const int* __restrict__ rmask,
    const float* __restrict__ elem_emb, const float* __restrict__ charge_emb,
    const float* __restrict__ aroma_emb, const float* __restrict__ react_emb,
    const float* __restrict__ seg_emb,   const float* __restrict__ pe)
{
    const int token = blockIdx.x * 4 + (threadIdx.x >> 6);
    const int c     = (threadIdx.x & 63) * 4;
    const int b     = token >> 9;
    const int l     = token & (LL - 1);

    const int e  = __ldg(&element[token]);
    const int a  = __ldg(&aroma[token]);
    const int ch = __ldg(&charge[token]) + 6;
    const int s  = __ldg(&segment[token]);
    const int r  = __ldg(&rmask[token]);

    float4 v = *(const float4*)(elem_emb + e * DD + c);
    float4 t;
    t = *(const float4*)(pe + l * DD + c);          v.x += t.x; v.y += t.y; v.z += t.z; v.w += t.w;
    t = *(const float4*)(aroma_emb + a * DD + c);   v.x += t.x; v.y += t.y; v.z += t.z; v.w += t.w;
    t = *(const float4*)(charge_emb + ch * DD + c); v.x += t.x; v.y += t.y; v.z += t.z; v.w += t.w;
    t = *(const float4*)(seg_emb + s * DD + c);     v.x += t.x; v.y += t.y; v.z += t.z; v.w += t.w;
    t = *(const float4*)(react_emb + r * DD + c);   v.x += t.x; v.y += t.y; v.z += t.z; v.w += t.w;

    *(float4*)(g_emb + (l * BB + b) * DD + c) = v;
    __half2 q0 = __float22half2_rn(make_float2(v.x, v.y));
    __half2 q1 = __float22half2_rn(make_float2(v.z, v.w));
    *(__half2*)(g_xh + token * DD + c)     = q0;
    *(__half2*)(g_xh + token * DD + c + 2) = q1;
}

// ---------------------------------------------------------------------------
// FP16 tensor-core GEMM via mma.sync.m16n8k16:  C = A @ W^T + bias (+res)(+relu)
// A, W fp16; accumulate fp32. BM=128, BN=128, BK=64 halves (128B rows),
// 3-stage cp.async pipeline, 256 threads (8 warps), warp tile 64x32.
// OUTH: store fp16 (feeds next GEMM); else store fp32 (msg).
// ---------------------------------------------------------------------------
#define BM     128
#define BN     128
#define BK     64
#define STAGES 3
#define STG_SZ 32768                  // (BM + BN) * BK * 2 bytes
#define SMEM_SZ (STAGES * STG_SZ)     // 98304
#define NTHR   256

template<int K, bool RELU, bool RES, bool OUTH>
__global__ __launch_bounds__(NTHR, 2) void hgemm_kernel(
    const __half* __restrict__ A, const __half* __restrict__ W,
    const float* __restrict__ bias, const __half* __restrict__ res,
    void* __restrict__ Cv, int N)
{
    extern __shared__ char smem[];
    const uint32_t sbase = smem_u32(smem);
    const int tid = threadIdx.x;
    const int wid = tid >> 5;
    const int lid = tid & 31;
    const int wm  = wid & 1;        // warp row: 2 x 64
    const int wn  = wid >> 1;       // warp col: 4 x 32

    const int rowBase = blockIdx.y * BM;
    const int colBase = blockIdx.x * BN;

    constexpr int NC = K / BK;

    // stage loader: A tile 128x64 fp16 (16KB) + B tile 128x64 fp16 (16KB)
    // smem row = 128B (64 halves), xor swizzle on 16B chunks: phys = ck^(r&7)
    auto load_stage = [&](int c, int buf) {
        const int k0 = c * BK;
        const uint32_t sA = sbase + buf * STG_SZ;
        const uint32_t sB = sA + 16384;
        const __half* Ag = A + (size_t)rowBase * K + k0;
        const __half* Wg = W + (size_t)colBase * K + k0;
        #pragma unroll
        for (int p = 0; p < 4; p++) {              // A: 1024 chunks / 256 thr
            int v = tid + p * NTHR;
            int r = v >> 3, ck = v & 7;
            cpasync16(sA + r * 128 + ((ck ^ (r & 7)) * 16),
                      Ag + (size_t)r * K + ck * 8);
        }
        #pragma unroll
        for (int p = 0; p < 4; p++) {              // B: 1024 chunks / 256 thr
            int v = tid + p * NTHR;
            int r = v >> 3, ck = v & 7;
            cpasync16(sB + r * 128 + ((ck ^ (r & 7)) * 16),
                      Wg + (size_t)r * K + ck * 8);
        }
        CP_COMMIT();
    };

    float acc[4][4][4];   // warp tile 64(4x16) x 32(4x8)
    #pragma unroll
    for (int mi = 0; mi < 4; mi++)
        #pragma unroll
        for (int ni = 0; ni < 4; ni++)
            #pragma unroll
            for (int j = 0; j < 4; j++) acc[mi][ni][j] = 0.f;

    // ldmatrix addressing (row stride 128B, 8 x 16B chunks per row)
    // A x4: sel bit0 -> +8 rows, bit1 -> +1 chunk = +8 k
    const int t   = lid & 7;
    const int sel = lid >> 3;
    int aRow[4], aXor[4];
    #pragma unroll
    for (int mi = 0; mi < 4; mi++) {
        int r = wm * 64 + mi * 16 + (sel & 1) * 8 + t;
        aRow[mi] = r * 128;
        aXor[mi] = r & 7;
    }
    const int aCk = sel >> 1;
    // B x4: sel bit0 -> +1 chunk (+8 k), bit1 -> +8 n rows
    int bRow[2], bXor[2];
    #pragma unroll
    for (int np = 0; np < 2; np++) {
        int r = wn * 32 + np * 16 + (sel >> 1) * 8 + t;
        bRow[np] = r * 128;
        bXor[np] = r & 7;
    }
    const int bCk = sel & 1;

    // prologue: stages 0, 1
    load_stage(0, 0);
    load_stage(1, 1);

    int cbuf = 0;
    for (int c = 0; c < NC; c++) {      // rolled (compile-time safe)
        cpwait<STAGES - 2>();
        __syncthreads();
        if (c + STAGES - 1 < NC) {
            int nbuf = cbuf + (STAGES - 1);
            if (nbuf >= STAGES) nbuf -= STAGES;
            load_stage(c + STAGES - 1, nbuf);
        } else {
            CP_COMMIT();
        }

        const uint32_t sA = sbase + cbuf * STG_SZ;
        const uint32_t sB = sA + 16384;

        #pragma unroll
        for (int ks = 0; ks < 4; ks++) {           // 4 x K=16 per chunk
            uint32_t af[4][4], bf[2][4];
            #pragma unroll
            for (int mi = 0; mi < 4; mi++) {
                int ck = ks * 2 + aCk;
                ldsm4(af[mi], sA + aRow[mi] + ((ck ^ aXor[mi]) * 16));
            }
            #pragma unroll
            for (int np = 0; np < 2; np++) {
                int ck = ks * 2 + bCk;
                ldsm4(bf[np], sB + bRow[np] + ((ck ^ bXor[np]) * 16));
            }
            #pragma unroll
            for (int mi = 0; mi < 4; mi++)
                #pragma unroll
                for (int ni = 0; ni < 4; ni++)
                    mma_f16(acc[mi][ni], af[mi], &bf[ni >> 1][(ni & 1) * 2]);
        }

        if (++cbuf == STAGES) cbuf = 0;
    }

    // ---- epilogue ----
    const int g  = lid >> 2;
    const int tg = lid & 3;
    #pragma unroll
    for (int mi = 0; mi < 4; mi++) {
        const int row0 = rowBase + wm * 64 + mi * 16 + g;
        const int row1 = row0 + 8;
        #pragma unroll
        for (int ni = 0; ni < 4; ni++) {
            const int col = colBase + wn * 32 + ni * 8 + tg * 2;
            float bx = __ldg(&bias[col]), by = __ldg(&bias[col + 1]);
            float2 v0 = make_float2(acc[mi][ni][0] + bx, acc[mi][ni][1] + by);
            float2 v1 = make_float2(acc[mi][ni][2] + bx, acc[mi][ni][3] + by);
            if (RES) {
                float2 r0 = __half22float2(*(const __half2*)(res + (size_t)row0 * N + col));
                float2 r1 = __half22float2(*(const __half2*)(res + (size_t)row1 * N + col));
                v0.x += r0.x; v0.y += r0.y; v1.x += r1.x; v1.y += r1.y;
            }
            if (RELU) {
                v0.x = fmaxf(v0.x, 0.f); v0.y = fmaxf(v0.y, 0.f);
                v1.x = fmaxf(v1.x, 0.f); v1.y = fmaxf(v1.y, 0.f);
            }
            if (OUTH) {
                __half* C = (__half*)Cv;
                *(__half2*)(C + (size_t)row0 * N + col) = __float22half2_rn(v0);
                *(__half2*)(C + (size_t)row1 * N + col) = __float22half2_rn(v1);
            } else {
                float* C = (float*)Cv;
                *(float2*)(C + (size_t)row0 * N + col) = v0;
                *(float2*)(C + (size_t)row1 * N + col) = v1;
            }
        }
    }
}

// ---------------------------------------------------------------------------
// Bond aggregation + output (fp32 exact)
// ---------------------------------------------------------------------------
__global__ __launch_bounds__(256) void agg_kernel(
    const int* __restrict__ bond, float* __restrict__ out)
{
    const int token = blockIdx.x * 4 + (threadIdx.x >> 6);
    const int c     = (threadIdx.x & 63) * 4;
    const int b     = token >> 9;
    const int l     = token & (LL - 1);

    float4 acc = *(const float4*)(g_emb + (l * BB + b) * DD + c);
    const int* bd = bond + token * KKB;
    #pragma unroll
    for (int k = 0; k < KKB; k++) {
        const int j = __ldg(&bd[k]);
        if (j != l) {
            float4 m = *(const float4*)(g_msg + ((size_t)b * LL + j) * DD + c);
            acc.x += m.x; acc.y += m.y; acc.z += m.z; acc.w += m.w;
        }
    }
    *(float4*)(out + (l * BB + b) * DD + c) = acc;
}

// ---------------------------------------------------------------------------
// Launch (graph-capturable)
// ---------------------------------------------------------------------------
extern "C" void kernel_launch(void* const* d_in, const int* in_sizes, int n_in,
                              void* d_out, int out_size)
{
    const int*   element    = (const int*)  d_in[0];
    const int*   bond       = (const int*)  d_in[1];
    const int*   aroma      = (const int*)  d_in[2];
    const int*   charge     = (const int*)  d_in[3];
    const int*   segment    = (const int*)  d_in[4];
    const int*   rmask      = (const int*)  d_in[5];
    const float* elem_emb   = (const float*)d_in[6];
    const float* charge_emb = (const float*)d_in[7];
    const float* aroma_emb  = (const float*)d_in[8];
    const float* react_emb  = (const float*)d_in[9];
    const float* seg_emb    = (const float*)d_in[10];
    const float* pe         = (const float*)d_in[11];
    const float* w1 = (const float*)d_in[12];
    const float* b1 = (const float*)d_in[13];
    const float* w2 = (const float*)d_in[14];
    const float* b2 = (const float*)d_in[15];
    const float* w3 = (const float*)d_in[16];
    const float* b3 = (const float*)d_in[17];
    const float* w4 = (const float*)d_in[18];
    const float* b4 = (const float*)d_in[19];
    const float* w5 = (const float*)d_in[20];
    const float* b5 = (const float*)d_in[21];

    __half *xh, *h, *x2, *x3, *wh;
    float *msg;
    cudaGetSymbolAddress((void**)&xh,  g_xh);
    cudaGetSymbolAddress((void**)&h,   g_h);
    cudaGetSymbolAddress((void**)&x2,  g_x2);
    cudaGetSymbolAddress((void**)&x3,  g_x3);
    cudaGetSymbolAddress((void**)&msg, g_msg);
    cudaGetSymbolAddress((void**)&wh,  g_wh);

    cudaFuncSetAttribute(hgemm_kernel<DD,  true,  false, true >,
                         cudaFuncAttributeMaxDynamicSharedMemorySize, SMEM_SZ);
    cudaFuncSetAttribute(hgemm_kernel<HID, false, true,  true >,
                         cudaFuncAttributeMaxDynamicSharedMemorySize, SMEM_SZ);
    cudaFuncSetAttribute(hgemm_kernel<DD,  false, false, false>,
                         cudaFuncAttributeMaxDynamicSharedMemorySize, SMEM_SZ);

    // 0) convert weights to fp16
    conv_w_kernel<<<(WTOTAL / 4 + 255) / 256, 256>>>(w1, w2, w3, w4, w5);

    // 1) embedding sum
    embed_kernel<<<MTOK / 4, 256>>>(element, aroma, charge, segment, rmask,
                                    elem_emb, charge_emb, aroma_emb,
                                    react_emb, seg_emb, pe);

    // 2) MLP block 1: h = relu(x @ w1^T + b1); x2 = x + h @ w2^T + b2
    hgemm_kernel<DD,  true,  false, true ><<<dim3(HID / BN, MTOK / BM), NTHR, SMEM_SZ>>>(
        xh, wh + WOFF_W1, b1, nullptr, h, HID);
    hgemm_kernel<HID, false, true,  true ><<<dim3(DD / BN,  MTOK / BM), NTHR, SMEM_SZ>>>(
        h, wh + WOFF_W2, b2, xh, x2, DD);

    // 3) MLP block 2
    hgemm_kernel<DD,  true,  false, true ><<<dim3(HID / BN, MTOK / BM), NTHR, SMEM_SZ>>>(
        x2, wh + WOFF_W3, b3, nullptr, h, HID);
    hgemm_kernel<HID, false, true,  true ><<<dim3(DD / BN,  MTOK / BM), NTHR, SMEM_SZ>>>(
        h, wh + WOFF_W4, b4, x2, x3, DD);

    // 4) msg = x3 @ w5^T + b5  (fp32 store)
    hgemm_kernel<DD,  false, false, false><<<dim3(DD / BN,  MTOK / BM), NTHR, SMEM_SZ>>>(
        x3, wh + WOFF_W5, b5, nullptr, msg, DD);

    // 5) out = emb + masked bond aggregation
    agg_kernel<<<MTOK / 4, 256>>>(bond, (float*)d_out);
}

// round 15
// speedup vs baseline: 1.9659x; 1.0303x over previous
#include <cuda_runtime.h>
#include <cuda_fp16.h>
#include <cstdint>

// Problem constants
#define BB   32
#define LL   512
#define DD   256
#define KKB  6
#define MTOK (BB * LL)   // 16384 tokens
#define HID  (4 * DD)    // 1024
#define HTOK (MTOK / 2)  // 8192 tokens per half-chain

// ---------------------------------------------------------------------------
// Scratch (static __device__ arrays: allocation-guard safe)
// ---------------------------------------------------------------------------
__device__ float  g_emb[MTOK * DD];   // [L][B][D] layout (exact fp32)
__device__ __half g_xh [MTOK * DD];   // [token][D], fp16 (GEMM input)
__device__ __half g_h  [MTOK * HID];  // hidden activations fp16
__device__ __half g_x2 [MTOK * DD];   // fp16
__device__ __half g_x3 [MTOK * DD];   // fp16
__device__ float  g_msg[MTOK * DD];   // exact fp32
// fp16 weights, concatenated: w1 | w2 | w3 | w4 | w5
#define WOFF_W1 0
#define WOFF_W2 262144
#define WOFF_W3 524288
#define WOFF_W4 786432
#define WOFF_W5 1048576
#define WTOTAL  1114112
__device__ __half g_wh[WTOTAL];

// ---------------------------------------------------------------------------
// PTX helpers (sm_80-compatible only: cp.async, ldmatrix, mma.sync)
// ---------------------------------------------------------------------------
__device__ __forceinline__ uint32_t smem_u32(const void* p) {
    uint32_t a;
    asm("{ .reg .u64 t; cvta.to.shared.u64 t, %1; cvt.u32.u64 %0, t; }"
        : "=r"(a) : "l"(p));
    return a;
}

__device__ __forceinline__ void cpasync16(uint32_t s, const void* g) {
    asm volatile("cp.async.cg.shared.global [%0], [%1], 16;" :: "r"(s), "l"(g));
}
#define CP_COMMIT() asm volatile("cp.async.commit_group;" ::: "memory")
template<int N> __device__ __forceinline__ void cpwait() {
    asm volatile("cp.async.wait_group %0;" :: "n"(N) : "memory");
}

__device__ __forceinline__ void ldsm4(uint32_t* r, uint32_t addr) {
    asm volatile("ldmatrix.sync.aligned.m8n8.x4.shared.b16 {%0,%1,%2,%3}, [%4];"
        : "=r"(r[0]), "=r"(r[1]), "=r"(r[2]), "=r"(r[3]) : "r"(addr));
}

// m16n8k16 fp16 mma, fp32 accumulate
__device__ __forceinline__ void mma_f16(float* d, const uint32_t* a, const uint32_t* b) {
    asm volatile(
        "mma.sync.aligned.m16n8k16.row.col.f32.f16.f16.f32 "
        "{%0,%1,%2,%3}, {%4,%5,%6,%7}, {%8,%9}, {%0,%1,%2,%3};"
        : "+f"(d[0]), "+f"(d[1]), "+f"(d[2]), "+f"(d[3])
        : "r"(a[0]), "r"(a[1]), "r"(a[2]), "r"(a[3]), "r"(b[0]), "r"(b[1]));
}

// ---------------------------------------------------------------------------
// Weight conversion: fp32 -> fp16 once.
// ---------------------------------------------------------------------------
__global__ __launch_bounds__(256) void conv_w_kernel(
    const float* __restrict__ w1, const float* __restrict__ w2,
    const float* __restrict__ w3, const float* __restrict__ w4,
    const float* __restrict__ w5)
{
    const int i = blockIdx.x * 256 + threadIdx.x;      // float4 index
    const size_t idx = (size_t)i * 4;
    if (idx >= WTOTAL) return;
    const float* s; size_t base;
    if      (idx < WOFF_W2) { s = w1; base = WOFF_W1; }
    else if (idx < WOFF_W3) { s = w2; base = WOFF_W2; }
    else if (idx < WOFF_W4) { s = w3; base = WOFF_W3; }
    else if (idx < WOFF_W5) { s = w4; base = WOFF_W4; }
    else                    { s = w5; base = WOFF_W5; }
    float4 v = *(const float4*)(s + (idx - base));
    __half2 h0 = __float22half2_rn(make_float2(v.x, v.y));
    __half2 h1 = __float22half2_rn(make_float2(v.z, v.w));
    *(__half2*)(g_wh + idx)     = h0;
    *(__half2*)(g_wh + idx + 2) = h1;
}

// ---------------------------------------------------------------------------
// Embedding sum: g_emb exact fp32; g_xh fp16 (GEMM input)
// ---------------------------------------------------------------------------
__global__ __launch_bounds__(256) void embed_kernel(
    const int* __restrict__ element, const int* __restrict__ aroma,
    const int* __restrict__ charge,  const int* __restrict__ segment,
    const int* __restrict__ rmask,
    const float* __restrict__ elem_emb, const float* __restrict__ charge_emb,
    const float* __restrict__ aroma_emb, const float* __restrict__ react_emb,
    const float* __restrict__ seg_emb,   const float* __restrict__ pe)
{
    const int token = blockIdx.x * 4 + (threadIdx.x >> 6);
    const int c     = (threadIdx.x & 63) * 4;
    const int b     = token >> 9;
    const int l     = token & (LL - 1);

    const int e  = __ldg(&element[token]);
    const int a  = __ldg(&aroma[token]);
    const int ch = __ldg(&charge[token]) + 6;
    const int s  = __ldg(&segment[token]);
    const int r  = __ldg(&rmask[token]);

    float4 v = *(const float4*)(elem_emb + e * DD + c);
    float4 t;
    t = *(const float4*)(pe + l * DD + c);          v.x += t.x; v.y += t.y; v.z += t.z; v.w += t.w;
    t = *(const float4*)(aroma_emb + a * DD + c);   v.x += t.x; v.y += t.y; v.z += t.z; v.w += t.w;
    t = *(const float4*)(charge_emb + ch * DD + c); v.x += t.x; v.y += t.y; v.z += t.z; v.w += t.w;
    t = *(const float4*)(seg_emb + s * DD + c);     v.x += t.x; v.y += t.y; v.z += t.z; v.w += t.w;
    t = *(const float4*)(react_emb + r * DD + c);   v.x += t.x; v.y += t.y; v.z += t.z; v.w += t.w;

    *(float4*)(g_emb + (l * BB + b) * DD + c) = v;
    __half2 q0 = __float22half2_rn(make_float2(v.x, v.y));
    __half2 q1 = __float22half2_rn(make_float2(v.z, v.w));
    *(__half2*)(g_xh + token * DD + c)     = q0;
    *(__half2*)(g_xh + token * DD + c + 2) = q1;
}

// ---------------------------------------------------------------------------
// FP16 tensor-core GEMM via mma.sync.m16n8k16:  C = A @ W^T + bias (+res)(+relu)
// A, W fp16; accumulate fp32. BM=128, BN=128, BK=64 halves (128B rows),
// 3-stage cp.async pipeline, 256 threads (8 warps), warp tile 64x32.
// OUTH: store fp16 (feeds next GEMM); else store fp32 (msg).
// ---------------------------------------------------------------------------
#define BM     128
#define BN     128
#define BK     64
#define STAGES 3
#define STG_SZ 32768                  // (BM + BN) * BK * 2 bytes
#define SMEM_SZ (STAGES * STG_SZ)     // 98304
#define NTHR   256

template<int K, bool RELU, bool RES, bool OUTH>
__global__ __launch_bounds__(NTHR, 2) void hgemm_kernel(
    const __half* __restrict__ A, const __half* __restrict__ W,
    const float* __restrict__ bias, const __half* __restrict__ res,
    void* __restrict__ Cv, int N)
{
    extern __shared__ char smem[];
    const uint32_t sbase = smem_u32(smem);
    const int tid = threadIdx.x;
    const int wid = tid >> 5;
    const int lid = tid & 31;
    const int wm  = wid & 1;        // warp row: 2 x 64
    const int wn  = wid >> 1;       // warp col: 4 x 32

    const int rowBase = blockIdx.y * BM;
    const int colBase = blockIdx.x * BN;

    constexpr int NC = K / BK;

    // stage loader: A tile 128x64 fp16 (16KB) + B tile 128x64 fp16 (16KB)
    // smem row = 128B (64 halves), xor swizzle on 16B chunks: phys = ck^(r&7)
    auto load_stage = [&](int c, int buf) {
        const int k0 = c * BK;
        const uint32_t sA = sbase + buf * STG_SZ;
        const uint32_t sB = sA + 16384;
        const __half* Ag = A + (size_t)rowBase * K + k0;
        const __half* Wg = W + (size_t)colBase * K + k0;
        #pragma unroll
        for (int p = 0; p < 4; p++) {              // A: 1024 chunks / 256 thr
            int v = tid + p * NTHR;
            int r = v >> 3, ck = v & 7;
            cpasync16(sA + r * 128 + ((ck ^ (r & 7)) * 16),
                      Ag + (size_t)r * K + ck * 8);
        }
        #pragma unroll
        for (int p = 0; p < 4; p++) {              // B: 1024 chunks / 256 thr
            int v = tid + p * NTHR;
            int r = v >> 3, ck = v & 7;
            cpasync16(sB + r * 128 + ((ck ^ (r & 7)) * 16),
                      Wg + (size_t)r * K + ck * 8);
        }
        CP_COMMIT();
    };

    float acc[4][4][4];   // warp tile 64(4x16) x 32(4x8)
    #pragma unroll
    for (int mi = 0; mi < 4; mi++)
        #pragma unroll
        for (int ni = 0; ni < 4; ni++)
            #pragma unroll
            for (int j = 0; j < 4; j++) acc[mi][ni][j] = 0.f;

    // ldmatrix addressing (row stride 128B, 8 x 16B chunks per row)
    const int t   = lid & 7;
    const int sel = lid >> 3;
    int aRow[4], aXor[4];
    #pragma unroll
    for (int mi = 0; mi < 4; mi++) {
        int r = wm * 64 + mi * 16 + (sel & 1) * 8 + t;
        aRow[mi] = r * 128;
        aXor[mi] = r & 7;
    }
    const int aCk = sel >> 1;
    int bRow[2], bXor[2];
    #pragma unroll
    for (int np = 0; np < 2; np++) {
        int r = wn * 32 + np * 16 + (sel >> 1) * 8 + t;
        bRow[np] = r * 128;
        bXor[np] = r & 7;
    }
    const int bCk = sel & 1;

    // prologue: stages 0, 1
    load_stage(0, 0);
    load_stage(1, 1);

    int cbuf = 0;
    for (int c = 0; c < NC; c++) {      // rolled (compile-time safe)
        cpwait<STAGES - 2>();
        __syncthreads();
        if (c + STAGES - 1 < NC) {
            int nbuf = cbuf + (STAGES - 1);
            if (nbuf >= STAGES) nbuf -= STAGES;
            load_stage(c + STAGES - 1, nbuf);
        } else {
            CP_COMMIT();
        }

        const uint32_t sA = sbase + cbuf * STG_SZ;
        const uint32_t sB = sA + 16384;

        #pragma unroll
        for (int ks = 0; ks < 4; ks++) {           // 4 x K=16 per chunk
            uint32_t af[4][4], bf[2][4];
            #pragma unroll
            for (int mi = 0; mi < 4; mi++) {
                int ck = ks * 2 + aCk;
                ldsm4(af[mi], sA + aRow[mi] + ((ck ^ aXor[mi]) * 16));
            }
            #pragma unroll
            for (int np = 0; np < 2; np++) {
                int ck = ks * 2 + bCk;
                ldsm4(bf[np], sB + bRow[np] + ((ck ^ bXor[np]) * 16));
            }
            #pragma unroll
            for (int mi = 0; mi < 4; mi++)
                #pragma unroll
                for (int ni = 0; ni < 4; ni++)
                    mma_f16(acc[mi][ni], af[mi], &bf[ni >> 1][(ni & 1) * 2]);
        }

        if (++cbuf == STAGES) cbuf = 0;
    }

    // ---- epilogue ----
    const int g  = lid >> 2;
    const int tg = lid & 3;
    #pragma unroll
    for (int mi = 0; mi < 4; mi++) {
        const int row0 = rowBase + wm * 64 + mi * 16 + g;
        const int row1 = row0 + 8;
        #pragma unroll
        for (int ni = 0; ni < 4; ni++) {
            const int col = colBase + wn * 32 + ni * 8 + tg * 2;
            float bx = __ldg(&bias[col]), by = __ldg(&bias[col + 1]);
            float2 v0 = make_float2(acc[mi][ni][0] + bx, acc[mi][ni][1] + by);
            float2 v1 = make_float2(acc[mi][ni][2] + bx, acc[mi][ni][3] + by);
            if (RES) {
                float2 r0 = __half22float2(*(const __half2*)(res + (size_t)row0 * N + col));
                float2 r1 = __half22float2(*(const __half2*)(res + (size_t)row1 * N + col));
                v0.x += r0.x; v0.y += r0.y; v1.x += r1.x; v1.y += r1.y;
            }
            if (RELU) {
                v0.x = fmaxf(v0.x, 0.f); v0.y = fmaxf(v0.y, 0.f);
                v1.x = fmaxf(v1.x, 0.f); v1.y = fmaxf(v1.y, 0.f);
            }
            if (OUTH) {
                __half* C = (__half*)Cv;
                *(__half2*)(C + (size_t)row0 * N + col) = __float22half2_rn(v0);
                *(__half2*)(C + (size_t)row1 * N + col) = __float22half2_rn(v1);
            } else {
                float* C = (float*)Cv;
                *(float2*)(C + (size_t)row0 * N + col) = v0;
                *(float2*)(C + (size_t)row1 * N + col) = v1;
            }
        }
    }
}

// ---------------------------------------------------------------------------
// Bond aggregation + output (fp32 exact)
// ---------------------------------------------------------------------------
__global__ __launch_bounds__(256) void agg_kernel(
    const int* __restrict__ bond, float* __restrict__ out)
{
    const int token = blockIdx.x * 4 + (threadIdx.x >> 6);
    const int c     = (threadIdx.x & 63) * 4;
    const int b     = token >> 9;
    const int l     = token & (LL - 1);

    float4 acc = *(const float4*)(g_emb + (l * BB + b) * DD + c);
    const int* bd = bond + token * KKB;
    #pragma unroll
    for (int k = 0; k < KKB; k++) {
        const int j = __ldg(&bd[k]);
        if (j != l) {
            float4 m = *(const float4*)(g_msg + ((size_t)b * LL + j) * DD + c);
            acc.x += m.x; acc.y += m.y; acc.z += m.z; acc.w += m.w;
        }
    }
    *(float4*)(out + (l * BB + b) * DD + c) = acc;
}

// ---------------------------------------------------------------------------
// Launch (graph-capturable; dual-stream pipelined token halves)
// ---------------------------------------------------------------------------
extern "C" void kernel_launch(void* const* d_in, const int* in_sizes, int n_in,
                              void* d_out, int out_size)
{
    const int*   element    = (const int*)  d_in[0];
    const int*   bond       = (const int*)  d_in[1];
    const int*   aroma      = (const int*)  d_in[2];
    const int*   charge     = (const int*)  d_in[3];
    const int*   segment    = (const int*)  d_in[4];
    const int*   rmask      = (const int*)  d_in[5];
    const float* elem_emb   = (const float*)d_in[6];
    const float* charge_emb = (const float*)d_in[7];
    const float* aroma_emb  = (const float*)d_in[8];
    const float* react_emb  = (const float*)d_in[9];
    const float* seg_emb    = (const float*)d_in[10];
    const float* pe         = (const float*)d_in[11];
    const float* w1 = (const float*)d_in[12];
    const float* b1 = (const float*)d_in[13];
    const float* w2 = (const float*)d_in[14];
    const float* b2 = (const float*)d_in[15];
    const float* w3 = (const float*)d_in[16];
    const float* b3 = (const float*)d_in[17];
    const float* w4 = (const float*)d_in[18];
    const float* b4 = (const float*)d_in[19];
    const float* w5 = (const float*)d_in[20];
    const float* b5 = (const float*)d_in[21];

    __half *xh, *h, *x2, *x3, *wh;
    float *msg;
    cudaGetSymbolAddress((void**)&xh,  g_xh);
    cudaGetSymbolAddress((void**)&h,   g_h);
    cudaGetSymbolAddress((void**)&x2,  g_x2);
    cudaGetSymbolAddress((void**)&x3,  g_x3);
    cudaGetSymbolAddress((void**)&msg, g_msg);
    cudaGetSymbolAddress((void**)&wh,  g_wh);

    cudaFuncSetAttribute(hgemm_kernel<DD,  true,  false, true >,
                         cudaFuncAttributeMaxDynamicSharedMemorySize, SMEM_SZ);
    cudaFuncSetAttribute(hgemm_kernel<HID, false, true,  true >,
                         cudaFuncAttributeMaxDynamicSharedMemorySize, SMEM_SZ);
    cudaFuncSetAttribute(hgemm_kernel<DD,  false, false, false>,
                         cudaFuncAttributeMaxDynamicSharedMemorySize, SMEM_SZ);

    // One-time side stream + fork/join events (created on first, uncaptured call)
    static cudaStream_t s1 = nullptr;
    static cudaEvent_t evFork, evConv, evEmb, evJoin;
    if (!s1) {
        cudaStreamCreateWithFlags(&s1, cudaStreamNonBlocking);
        cudaEventCreateWithFlags(&evFork, cudaEventDisableTiming);
        cudaEventCreateWithFlags(&evConv, cudaEventDisableTiming);
        cudaEventCreateWithFlags(&evEmb,  cudaEventDisableTiming);
        cudaEventCreateWithFlags(&evJoin, cudaEventDisableTiming);
    }

    // fork: s1 starts at entry, runs weight conversion concurrently w/ embed
    cudaEventRecord(evFork, 0);
    cudaStreamWaitEvent(s1, evFork, 0);
    conv_w_kernel<<<(WTOTAL / 4 + 255) / 256, 256, 0, s1>>>(w1, w2, w3, w4, w5);
    cudaEventRecord(evConv, s1);

    embed_kernel<<<MTOK / 4, 256>>>(element, aroma, charge, segment, rmask,
                                    elem_emb, charge_emb, aroma_emb,
                                    react_emb, seg_emb, pe);
    cudaEventRecord(evEmb, 0);

    // cross-sync: chain A (stream 0) needs conv_w; chain B (s1) needs embed
    cudaStreamWaitEvent(0,  evConv, 0);
    cudaStreamWaitEvent(s1, evEmb,  0);

    const dim3 gBig(HID / BN, HTOK / BM);   // (8, 64)
    const dim3 gSml(DD  / BN, HTOK / BM);   // (1, 64)... DD/BN = 2 -> (2, 64)

    // ---- chain A: token half 0 on stream 0 ----
    {
        const size_t oD = 0, oH = 0;
        hgemm_kernel<DD,  true,  false, true ><<<gBig, NTHR, SMEM_SZ>>>(
            xh + oD, wh + WOFF_W1, b1, nullptr, h + oH, HID);
        hgemm_kernel<HID, false, true,  true ><<<gSml, NTHR, SMEM_SZ>>>(
            h + oH, wh + WOFF_W2, b2, xh + oD, x2 + oD, DD);
        hgemm_kernel<DD,  true,  false, true ><<<gBig, NTHR, SMEM_SZ>>>(
            x2 + oD, wh + WOFF_W3, b3, nullptr, h + oH, HID);
        hgemm_kernel<HID, false, true,  true ><<<gSml, NTHR, SMEM_SZ>>>(
            h + oH, wh + WOFF_W4, b4, x2 + oD, x3 + oD, DD);
        hgemm_kernel<DD,  false, false, false><<<gSml, NTHR, SMEM_SZ>>>(
            x3 + oD, wh + WOFF_W5, b5, nullptr, msg + oD, DD);
    }

    // ---- chain B: token half 1 on stream s1 ----
    {
        const size_t oD = (size_t)HTOK * DD, oH = (size_t)HTOK * HID;
        hgemm_kernel<DD,  true,  false, true ><<<gBig, NTHR, SMEM_SZ, s1>>>(
            xh + oD, wh + WOFF_W1, b1, nullptr, h + oH, HID);
        hgemm_kernel<HID, false, true,  true ><<<gSml, NTHR, SMEM_SZ, s1>>>(
            h + oH, wh + WOFF_W2, b2, xh + oD, x2 + oD, DD);
        hgemm_kernel<DD,  true,  false, true ><<<gBig, NTHR, SMEM_SZ, s1>>>(
            x2 + oD, wh + WOFF_W3, b3, nullptr, h + oH, HID);
        hgemm_kernel<HID, false, true,  true ><<<gSml, NTHR, SMEM_SZ, s1>>>(
            h + oH, wh + WOFF_W4, b4, x2 + oD, x3 + oD, DD);
        hgemm_kernel<DD,  false, false, false><<<gSml, NTHR, SMEM_SZ, s1>>>(
            x3 + oD, wh + WOFF_W5, b5, nullptr, (float*)msg + oD, DD);
    }

    // join: agg needs both halves of msg
    cudaEventRecord(evJoin, s1);
    cudaStreamWaitEvent(0, evJoin, 0);

    agg_kernel<<<MTOK / 4, 256>>>(bond, (float*)d_out);
}

// round 17
// speedup vs baseline: 2.0434x; 1.0394x over previous
#include <cuda_runtime.h>
#include <cuda_fp16.h>
#include <cstdint>

// Problem constants
#define BB   32
#define LL   512
#define DD   256
#define KKB  6
#define MTOK (BB * LL)   // 16384 tokens
#define HID  (4 * DD)    // 1024
#define NCHAIN 4
#define QTOK (MTOK / NCHAIN)   // 4096 tokens per chain (8 whole batches)

// ---------------------------------------------------------------------------
// Scratch (static __device__ arrays: allocation-guard safe)
// ---------------------------------------------------------------------------
__device__ float  g_emb[MTOK * DD];   // [L][B][D] layout (exact fp32)
__device__ __half g_xh [MTOK * DD];   // [token][D], fp16 (GEMM input)
__device__ __half g_h  [MTOK * HID];  // hidden activations fp16
__device__ __half g_x2 [MTOK * DD];   // fp16
__device__ __half g_x3 [MTOK * DD];   // fp16
__device__ float  g_msg[MTOK * DD];   // exact fp32
// fp16 weights, concatenated: w1 | w2 | w3 | w4 | w5
#define WOFF_W1 0
#define WOFF_W2 262144
#define WOFF_W3 524288
#define WOFF_W4 786432
#define WOFF_W5 1048576
#define WTOTAL  1114112
__device__ __half g_wh[WTOTAL];

// ---------------------------------------------------------------------------
// PTX helpers (sm_80-compatible only: cp.async, ldmatrix, mma.sync)
// ---------------------------------------------------------------------------
__device__ __forceinline__ uint32_t smem_u32(const void* p) {
    uint32_t a;
    asm("{ .reg .u64 t; cvta.to.shared.u64 t, %1; cvt.u32.u64 %0, t; }"
        : "=r"(a) : "l"(p));
    return a;
}

__device__ __forceinline__ void cpasync16(uint32_t s, const void* g) {
    asm volatile("cp.async.cg.shared.global [%0], [%1], 16;" :: "r"(s), "l"(g));
}
#define CP_COMMIT() asm volatile("cp.async.commit_group;" ::: "memory")
template<int N> __device__ __forceinline__ void cpwait() {
    asm volatile("cp.async.wait_group %0;" :: "n"(N) : "memory");
}

__device__ __forceinline__ void ldsm4(uint32_t* r, uint32_t addr) {
    asm volatile("ldmatrix.sync.aligned.m8n8.x4.shared.b16 {%0,%1,%2,%3}, [%4];"
        : "=r"(r[0]), "=r"(r[1]), "=r"(r[2]), "=r"(r[3]) : "r"(addr));
}

// m16n8k16 fp16 mma, fp32 accumulate
__device__ __forceinline__ void mma_f16(float* d, const uint32_t* a, const uint32_t* b) {
    asm volatile(
        "mma.sync.aligned.m16n8k16.row.col.f32.f16.f16.f32 "
        "{%0,%1,%2,%3}, {%4,%5,%6,%7}, {%8,%9}, {%0,%1,%2,%3};"
        : "+f"(d[0]), "+f"(d[1]), "+f"(d[2]), "+f"(d[3])
        : "r"(a[0]), "r"(a[1]), "r"(a[2]), "r"(a[3]), "r"(b[0]), "r"(b[1]));
}

// ---------------------------------------------------------------------------
// Weight conversion: fp32 -> fp16 once.
// ---------------------------------------------------------------------------
__global__ __launch_bounds__(256) void conv_w_kernel(
    const float* __restrict__ w1, const float* __restrict__ w2,
    const float* __restrict__ w3, const float* __restrict__ w4,
    const float* __restrict__ w5)
{
    const int i = blockIdx.x * 256 + threadIdx.x;      // float4 index
    const size_t idx = (size_t)i * 4;
    if (idx >= WTOTAL) return;
    const float* s; size_t base;
    if      (idx < WOFF_W2) { s = w1; base = WOFF_W1; }
    else if (idx < WOFF_W3) { s = w2; base = WOFF_W2; }
    else if (idx < WOFF_W4) { s = w3; base = WOFF_W3; }
    else if (idx < WOFF_W5) { s = w4; base = WOFF_W4; }
    else                    { s = w5; base = WOFF_W5; }
    float4 v = *(const float4*)(s + (idx - base));
    __half2 h0 = __float22half2_rn(make_float2(v.x, v.y));
    __half2 h1 = __float22half2_rn(make_float2(v.z, v.w));
    *(__half2*)(g_wh + idx)     = h0;
    *(__half2*)(g_wh + idx + 2) = h1;
}

// ---------------------------------------------------------------------------
// Embedding sum: g_emb exact fp32; g_xh fp16 (GEMM input)
// Token-offset version so each chain embeds its own quarter.
// ---------------------------------------------------------------------------
__global__ __launch_bounds__(256) void embed_kernel(
    const int* __restrict__ element, const int* __restrict__ aroma,
    const int* __restrict__ charge,  const int* __restrict__ segment,
    const int* __restrict__ rmask,
    const float* __restrict__ elem_emb, const float* __restrict__ charge_emb,
    const float* __restrict__ aroma_emb, const float* __restrict__ react_emb,
    const float* __restrict__ seg_emb,   const float* __restrict__ pe,
    int tok0)
{
    const int token = tok0 + blockIdx.x * 4 + (threadIdx.x >> 6);
    const int c     = (threadIdx.x & 63) * 4;
    const int b     = token >> 9;
    const int l     = token & (LL - 1);

    const int e  = __ldg(&element[token]);
    const int a  = __ldg(&aroma[token]);
    const int ch = __ldg(&charge[token]) + 6;
    const int s  = __ldg(&segment[token]);
    const int r  = __ldg(&rmask[token]);

    float4 v = *(const float4*)(elem_emb + e * DD + c);
    float4 t;
    t = *(const float4*)(pe + l * DD + c);          v.x += t.x; v.y += t.y; v.z += t.z; v.w += t.w;
    t = *(const float4*)(aroma_emb + a * DD + c);   v.x += t.x; v.y += t.y; v.z += t.z; v.w += t.w;
    t = *(const float4*)(charge_emb + ch * DD + c); v.x += t.x; v.y += t.y; v.z += t.z; v.w += t.w;
    t = *(const float4*)(seg_emb + s * DD + c);     v.x += t.x; v.y += t.y; v.z += t.z; v.w += t.w;
    t = *(const float4*)(react_emb + r * DD + c);   v.x += t.x; v.y += t.y; v.z += t.z; v.w += t.w;

    *(float4*)(g_emb + (l * BB + b) * DD + c) = v;
    __half2 q0 = __float22half2_rn(make_float2(v.x, v.y));
    __half2 q1 = __float22half2_rn(make_float2(v.z, v.w));
    *(__half2*)(g_xh + (size_t)token * DD + c)     = q0;
    *(__half2*)(g_xh + (size_t)token * DD + c + 2) = q1;
}

// ---------------------------------------------------------------------------
// FP16 tensor-core GEMM via mma.sync.m16n8k16:  C = A @ W^T + bias (+res)(+relu)
// A, W fp16; accumulate fp32. BM=128, BN=128, BK=64 halves (128B rows),
// 3-stage cp.async pipeline, 256 threads (8 warps), warp tile 64x32.
// OUTH: store fp16 (feeds next GEMM); else store fp32 (msg).
// ---------------------------------------------------------------------------
#define BM     128
#define BN     128
#define BK     64
#define STAGES 3
#define STG_SZ 32768                  // (BM + BN) * BK * 2 bytes
#define SMEM_SZ (STAGES * STG_SZ)     // 98304
#define NTHR   256

template<int K, bool RELU, bool RES, bool OUTH>
__global__ __launch_bounds__(NTHR, 2) void hgemm_kernel(
    const __half* __restrict__ A, const __half* __restrict__ W,
    const float* __restrict__ bias, const __half* __restrict__ res,
    void* __restrict__ Cv, int N)
{
    extern __shared__ char smem[];
    const uint32_t sbase = smem_u32(smem);
    const int tid = threadIdx.x;
    const int wid = tid >> 5;
    const int lid = tid & 31;
    const int wm  = wid & 1;        // warp row: 2 x 64
    const int wn  = wid >> 1;       // warp col: 4 x 32

    const int rowBase = blockIdx.y * BM;
    const int colBase = blockIdx.x * BN;

    constexpr int NC = K / BK;

    // stage loader: A tile 128x64 fp16 (16KB) + B tile 128x64 fp16 (16KB)
    // smem row = 128B (64 halves), xor swizzle on 16B chunks: phys = ck^(r&7)
    auto load_stage = [&](int c, int buf) {
        const int k0 = c * BK;
        const uint32_t sA = sbase + buf * STG_SZ;
        const uint32_t sB = sA + 16384;
        const __half* Ag = A + (size_t)rowBase * K + k0;
        const __half* Wg = W + (size_t)colBase * K + k0;
        #pragma unroll
        for (int p = 0; p < 4; p++) {              // A: 1024 chunks / 256 thr
            int v = tid + p * NTHR;
            int r = v >> 3, ck = v & 7;
            cpasync16(sA + r * 128 + ((ck ^ (r & 7)) * 16),
                      Ag + (size_t)r * K + ck * 8);
        }
        #pragma unroll
        for (int p = 0; p < 4; p++) {              // B: 1024 chunks / 256 thr
            int v = tid + p * NTHR;
            int r = v >> 3, ck = v & 7;
            cpasync16(sB + r * 128 + ((ck ^ (r & 7)) * 16),
                      Wg + (size_t)r * K + ck * 8);
        }
        CP_COMMIT();
    };

    float acc[4][4][4];   // warp tile 64(4x16) x 32(4x8)
    #pragma unroll
    for (int mi = 0; mi < 4; mi++)
        #pragma unroll
        for (int ni = 0; ni < 4; ni++)
            #pragma unroll
            for (int j = 0; j < 4; j++) acc[mi][ni][j] = 0.f;

    // ldmatrix addressing (row stride 128B, 8 x 16B chunks per row)
    const int t   = lid & 7;
    const int sel = lid >> 3;
    int aRow[4], aXor[4];
    #pragma unroll
    for (int mi = 0; mi < 4; mi++) {
        int r = wm * 64 + mi * 16 + (sel & 1) * 8 + t;
        aRow[mi] = r * 128;
        aXor[mi] = r & 7;
    }
    const int aCk = sel >> 1;
    int bRow[2], bXor[2];
    #pragma unroll
    for (int np = 0; np < 2; np++) {
        int r = wn * 32 + np * 16 + (sel >> 1) * 8 + t;
        bRow[np] = r * 128;
        bXor[np] = r & 7;
    }
    const int bCk = sel & 1;

    // prologue: stages 0, 1
    load_stage(0, 0);
    load_stage(1, 1);

    int cbuf = 0;
    for (int c = 0; c < NC; c++) {      // rolled (compile-time safe)
        cpwait<STAGES - 2>();
        __syncthreads();
        if (c + STAGES - 1 < NC) {
            int nbuf = cbuf + (STAGES - 1);
            if (nbuf >= STAGES) nbuf -= STAGES;
            load_stage(c + STAGES - 1, nbuf);
        } else {
            CP_COMMIT();
        }

        const uint32_t sA = sbase + cbuf * STG_SZ;
        const uint32_t sB = sA + 16384;

        #pragma unroll
        for (int ks = 0; ks < 4; ks++) {           // 4 x K=16 per chunk
            uint32_t af[4][4], bf[2][4];
            #pragma unroll
            for (int mi = 0; mi < 4; mi++) {
                int ck = ks * 2 + aCk;
                ldsm4(af[mi], sA + aRow[mi] + ((ck ^ aXor[mi]) * 16));
            }
            #pragma unroll
            for (int np = 0; np < 2; np++) {
                int ck = ks * 2 + bCk;
                ldsm4(bf[np], sB + bRow[np] + ((ck ^ bXor[np]) * 16));
            }
            #pragma unroll
            for (int mi = 0; mi < 4; mi++)
                #pragma unroll
                for (int ni = 0; ni < 4; ni++)
                    mma_f16(acc[mi][ni], af[mi], &bf[ni >> 1][(ni & 1) * 2]);
        }

        if (++cbuf == STAGES) cbuf = 0;
    }

    // ---- epilogue ----
    const int g  = lid >> 2;
    const int tg = lid & 3;
    #pragma unroll
    for (int mi = 0; mi < 4; mi++) {
        const int row0 = rowBase + wm * 64 + mi * 16 + g;
        const int row1 = row0 + 8;
        #pragma unroll
        for (int ni = 0; ni < 4; ni++) {
            const int col = colBase + wn * 32 + ni * 8 + tg * 2;
            float bx = __ldg(&bias[col]), by = __ldg(&bias[col + 1]);
            float2 v0 = make_float2(acc[mi][ni][0] + bx, acc[mi][ni][1] + by);
            float2 v1 = make_float2(acc[mi][ni][2] + bx, acc[mi][ni][3] + by);
            if (RES) {
                float2 r0 = __half22float2(*(const __half2*)(res + (size_t)row0 * N + col));
                float2 r1 = __half22float2(*(const __half2*)(res + (size_t)row1 * N + col));
                v0.x += r0.x; v0.y += r0.y; v1.x += r1.x; v1.y += r1.y;
            }
            if (RELU) {
                v0.x = fmaxf(v0.x, 0.f); v0.y = fmaxf(v0.y, 0.f);
                v1.x = fmaxf(v1.x, 0.f); v1.y = fmaxf(v1.y, 0.f);
            }
            if (OUTH) {
                __half* C = (__half*)Cv;
                *(__half2*)(C + (size_t)row0 * N + col) = __float22half2_rn(v0);
                *(__half2*)(C + (size_t)row1 * N + col) = __float22half2_rn(v1);
            } else {
                float* C = (float*)Cv;
                *(float2*)(C + (size_t)row0 * N + col) = v0;
                *(float2*)(C + (size_t)row1 * N + col) = v1;
            }
        }
    }
}

// ---------------------------------------------------------------------------
// Bond aggregation + output (fp32 exact), token-offset version.
// bond[b,l,k] indexes l within the SAME batch b, and chains own whole
// batches, so per-chain agg needs only its own msg quarter.
// ---------------------------------------------------------------------------
__global__ __launch_bounds__(256) void agg_kernel(
    const int* __restrict__ bond, float* __restrict__ out, int tok0)
{
    const int token = tok0 + blockIdx.x * 4 + (threadIdx.x >> 6);
    const int c     = (threadIdx.x & 63) * 4;
    const int b     = token >> 9;
    const int l     = token & (LL - 1);

    float4 acc = *(const float4*)(g_emb + (l * BB + b) * DD + c);
    const int* bd = bond + (size_t)token * KKB;
    #pragma unroll
    for (int k = 0; k < KKB; k++) {
        const int j = __ldg(&bd[k]);
        if (j != l) {
            float4 m = *(const float4*)(g_msg + ((size_t)b * LL + j) * DD + c);
            acc.x += m.x; acc.y += m.y; acc.z += m.z; acc.w += m.w;
        }
    }
    *(float4*)(out + (l * BB + b) * DD + c) = acc;
}

// ---------------------------------------------------------------------------
// Launch (graph-capturable; 4 pipelined chains on 4 streams)
// ---------------------------------------------------------------------------
extern "C" void kernel_launch(void* const* d_in, const int* in_sizes, int n_in,
                              void* d_out, int out_size)
{
    const int*   element    = (const int*)  d_in[0];
    const int*   bond       = (const int*)  d_in[1];
    const int*   aroma      = (const int*)  d_in[2];
    const int*   charge     = (const int*)  d_in[3];
    const int*   segment    = (const int*)  d_in[4];
    const int*   rmask      = (const int*)  d_in[5];
    const float* elem_emb   = (const float*)d_in[6];
    const float* charge_emb = (const float*)d_in[7];
    const float* aroma_emb  = (const float*)d_in[8];
    const float* react_emb  = (const float*)d_in[9];
    const float* seg_emb    = (const float*)d_in[10];
    const float* pe         = (const float*)d_in[11];
    const float* w1 = (const float*)d_in[12];
    const float* b1 = (const float*)d_in[13];
    const float* w2 = (const float*)d_in[14];
    const float* b2 = (const float*)d_in[15];
    const float* w3 = (const float*)d_in[16];
    const float* b3 = (const float*)d_in[17];
    const float* w4 = (const float*)d_in[18];
    const float* b4 = (const float*)d_in[19];
    const float* w5 = (const float*)d_in[20];
    const float* b5 = (const float*)d_in[21];

    __half *xh, *h, *x2, *x3, *wh;
    float *msg;
    cudaGetSymbolAddress((void**)&xh,  g_xh);
    cudaGetSymbolAddress((void**)&h,   g_h);
    cudaGetSymbolAddress((void**)&x2,  g_x2);
    cudaGetSymbolAddress((void**)&x3,  g_x3);
    cudaGetSymbolAddress((void**)&msg, g_msg);
    cudaGetSymbolAddress((void**)&wh,  g_wh);

    cudaFuncSetAttribute(hgemm_kernel<DD,  true,  false, true >,
                         cudaFuncAttributeMaxDynamicSharedMemorySize, SMEM_SZ);
    cudaFuncSetAttribute(hgemm_kernel<HID, false, true,  true >,
                         cudaFuncAttributeMaxDynamicSharedMemorySize, SMEM_SZ);
    cudaFuncSetAttribute(hgemm_kernel<DD,  false, false, false>,
                         cudaFuncAttributeMaxDynamicSharedMemorySize, SMEM_SZ);

    // One-time streams + events (created on first, uncaptured call)
    static cudaStream_t st[NCHAIN] = {nullptr, nullptr, nullptr, nullptr};
    static cudaEvent_t evFork, evConv, evDone[NCHAIN];
    if (!st[1]) {
        st[0] = 0;  // default stream = chain 0
        for (int i = 1; i < NCHAIN; i++)
            cudaStreamCreateWithFlags(&st[i], cudaStreamNonBlocking);
        cudaEventCreateWithFlags(&evFork, cudaEventDisableTiming);
        cudaEventCreateWithFlags(&evConv, cudaEventDisableTiming);
        for (int i = 0; i < NCHAIN; i++)
            cudaEventCreateWithFlags(&evDone[i], cudaEventDisableTiming);
    }

    // fork side streams from stream 0
    cudaEventRecord(evFork, 0);
    for (int i = 1; i < NCHAIN; i++) cudaStreamWaitEvent(st[i], evFork, 0);

    // weight conversion on chain-1 stream; all chains wait on it
    conv_w_kernel<<<(WTOTAL / 4 + 255) / 256, 256, 0, st[1]>>>(w1, w2, w3, w4, w5);
    cudaEventRecord(evConv, st[1]);
    cudaStreamWaitEvent(st[0], evConv, 0);
    cudaStreamWaitEvent(st[2], evConv, 0);
    cudaStreamWaitEvent(st[3], evConv, 0);

    const dim3 gBig(HID / BN, QTOK / BM);   // (8, 32)
    const dim3 gSml(DD  / BN, QTOK / BM);   // (2, 32)

    for (int i = 0; i < NCHAIN; i++) {
        cudaStream_t s = st[i];
        const int    tok0 = i * QTOK;
        const size_t oD = (size_t)tok0 * DD, oH = (size_t)tok0 * HID;

        // per-chain embed (its own quarter of tokens)
        embed_kernel<<<QTOK / 4, 256, 0, s>>>(element, aroma, charge, segment,
                                              rmask, elem_emb, charge_emb,
                                              aroma_emb, react_emb, seg_emb,
                                              pe, tok0);

        hgemm_kernel<DD,  true,  false, true ><<<gBig, NTHR, SMEM_SZ, s>>>(
            xh + oD, wh + WOFF_W1, b1, nullptr, h + oH, HID);
        hgemm_kernel<HID, false, true,  true ><<<gSml, NTHR, SMEM_SZ, s>>>(
            h + oH, wh + WOFF_W2, b2, xh + oD, x2 + oD, DD);
        hgemm_kernel<DD,  true,  false, true ><<<gBig, NTHR, SMEM_SZ, s>>>(
            x2 + oD, wh + WOFF_W3, b3, nullptr, h + oH, HID);
        hgemm_kernel<HID, false, true,  true ><<<gSml, NTHR, SMEM_SZ, s>>>(
            h + oH, wh + WOFF_W4, b4, x2 + oD, x3 + oD, DD);
        hgemm_kernel<DD,  false, false, false><<<gSml, NTHR, SMEM_SZ, s>>>(
            x3 + oD, wh + WOFF_W5, b5, nullptr, msg + oD, DD);

        // per-chain aggregation + output (batches are chain-local)
        agg_kernel<<<QTOK / 4, 256, 0, s>>>(bond, (float*)d_out, tok0);
    }

    // join all side streams back into stream 0 (capture validity + completion)
    for (int i = 1; i < NCHAIN; i++) {
        cudaEventRecord(evDone[i], st[i]);
        cudaStreamWaitEvent(st[0], evDone[i], 0);
    }
}